// round 12
// baseline (speedup 1.0000x reference)
#include <cuda_runtime.h>
#include <cuda_bf16.h>
#include <math.h>
#include <stdint.h>

// Problem constants
#define BB 16      // batch
#define TT 64      // seq len
#define VV 50257   // vocab
#define EE 512     // embed
#define HH 1024    // hidden
#define G3H 3072   // 3*H

#define NCTA_SCAN 128   // persistent scan grid (<=148 SMs -> all resident)

// ---------------- scratch (no allocations allowed) ----------------
__device__ float g_x0[BB * 2 * EE];          // 16x1024
__device__ float g_h0a[BB * HH];             // layer0 h0
__device__ float g_h0b[BB * HH];             // layer1 h0
__device__ float g_xdec[TT * BB * 2 * EE];   // 1024x1024
__device__ float g_xp[TT * BB * G3H];        // 1024x3072 (reused for both layers)
__device__ float g_ys0[TT * BB * HH];        // 1024x1024
__device__ float g_ys1[TT * BB * HH];        // 1024x1024
__device__ float g_final[TT * BB * EE];      // 1024x512

// legacy contended barrier (used ONCE per scan launch to zero the flag array;
// self-restoring: count returns to 0; gen compared by equality)
__device__ unsigned g_bar_count = 0;
__device__ unsigned g_bar_gen   = 0;
// distributed flag barrier: one slot per CTA, zeroed at scan start
__device__ unsigned g_arrive2[NCTA_SCAN];

// ---------------- small builders ----------------
__global__ void build_x0(const float* __restrict__ init, float* __restrict__ x0) {
    int b = blockIdx.x;
    for (int c = threadIdx.x; c < EE; c += blockDim.x) {
        float v = init[b * EE + c];
        x0[b * (2 * EE) + c] = v;
        x0[b * (2 * EE) + EE + c] = v;
    }
}

__global__ void build_xdec(const int* __restrict__ helper,
                           const float* __restrict__ emb,
                           const float* __restrict__ init,
                           float* __restrict__ xdec) {
    int r = blockIdx.x;            // r = t*B + b
    int t = r >> 4;
    int b = r & 15;
    int tok = helper[b * TT + t];
    const float* src0 = emb + (size_t)tok * EE;
    const float* src1 = init + b * EE;
    float* dst = xdec + (size_t)r * (2 * EE);
    for (int c = threadIdx.x; c < EE; c += blockDim.x) {
        dst[c] = src0[c];
        dst[EE + c] = src1[c];
    }
}

// ---------------- tf32 helpers ----------------
__device__ __forceinline__ uint32_t f2tf32(float x) {
    uint32_t r;
    asm("cvt.rna.tf32.f32 %0, %1;" : "=r"(r) : "f"(x));
    return r;
}

__device__ __forceinline__ void mma_tf32(float* c, const uint32_t* a, const uint32_t* b) {
    asm volatile(
        "mma.sync.aligned.m16n8k8.row.col.f32.tf32.tf32.f32 "
        "{%0,%1,%2,%3}, {%4,%5,%6,%7}, {%8,%9}, {%0,%1,%2,%3};"
        : "+f"(c[0]), "+f"(c[1]), "+f"(c[2]), "+f"(c[3])
        : "r"(a[0]), "r"(a[1]), "r"(a[2]), "r"(a[3]), "r"(b[0]), "r"(b[1]));
}

// ---------------- tensor-core GEMM: C = A(MxK) * B(NxK)^T ----------------
// Block tile 128x128, K tile 32. 8 warps: warp (wm,wn) owns 64x32.
// Grid: blockIdx.x = M-tile (FAST axis), blockIdx.y = N-tile (B-tile L2 reuse).
// Double-buffered with compile-time stage offsets; one __syncthreads per K-tile.
// ks-XOR bank swizzle on fragment rows (STS conflict 4 -> 1).
// flags: bit0 = add bias[n]; bit1 = tanh; bit2 = (b,t) transposed store (logits)
// COMP: compensated tf32 split (Ah*Bh + Al*Bh + Ah*Bl) ~ fp32 accuracy.

#define STG_FAST 8192    // floats per stage: Ah(4096)+Bh(4096)
#define STG_COMP 16384   // + Al(4096)+Bl(4096)

template<bool COMP>
__device__ __forceinline__ void load_tile(
    const float* __restrict__ A, const float* __restrict__ B,
    int M, int N, int K, int m0, int n0, int kbase, int lrow,
    float4* pa, float4* pb) {
#pragma unroll
    for (int p = 0; p < 4; p++) {
        int gr = m0 + lrow + p * 32;
        pa[p] = (gr < M) ? *(const float4*)&A[(size_t)gr * K + kbase]
                         : make_float4(0.f, 0.f, 0.f, 0.f);
        int gn = n0 + lrow + p * 32;
        pb[p] = (gn < N) ? *(const float4*)&B[(size_t)gn * K + kbase]
                         : make_float4(0.f, 0.f, 0.f, 0.f);
    }
}

template<bool COMP>
__device__ __forceinline__ void store_stage(
    float* stage, const float4* pa, const float4* pb, int lrow, int lk4) {
    float* Ah = stage;
    float* Bh = stage + 4096;
    float* Al = COMP ? (stage + 8192)  : nullptr;
    float* Bl = COMP ? (stage + 12288) : nullptr;
#pragma unroll
    for (int p = 0; p < 4; p++) {
        int m = lrow + p * 32;
        const float* av = (const float*)&pa[p];
        const float* bv = (const float*)&pb[p];
#pragma unroll
        for (int i = 0; i < 4; i++) {
            int k = lk4 + i;
            int ks = k >> 3, kc = k & 7;
            {
                int mt = m >> 4, r = m & 15;
                int ln = (((r & 7) << 2) | (kc & 3)) ^ ks;
                int slot = (r >> 3) | ((kc >> 2) << 1);
                int idx = (((ks * 8 + mt) * 32 + ln) << 2) | slot;
                float x = av[i];
                uint32_t hb = f2tf32(x);
                Ah[idx] = __uint_as_float(hb);
                if (COMP) Al[idx] = __uint_as_float(f2tf32(x - __uint_as_float(hb)));
            }
            {
                int nt = m >> 3;
                int ln = (((m & 7) << 2) | (kc & 3)) ^ ks;
                int slot = kc >> 2;
                int idx = (((ks * 16 + nt) * 32 + ln) << 1) | slot;
                float x = bv[i];
                uint32_t hb = f2tf32(x);
                Bh[idx] = __uint_as_float(hb);
                if (COMP) Bl[idx] = __uint_as_float(f2tf32(x - __uint_as_float(hb)));
            }
        }
    }
}

template<bool COMP>
__device__ __forceinline__ void compute_stage(
    const float* stage, float acc[4][4][4], int wm, int wn, int lane) {
    const float* Ah = stage;
    const float* Bh = stage + 4096;
    const float* Al = COMP ? (stage + 8192)  : nullptr;
    const float* Bl = COMP ? (stage + 12288) : nullptr;
#pragma unroll
    for (int ks = 0; ks < 4; ks++) {
        const int lsw = lane ^ ks;
        uint32_t af[4][4], bf[4][2];
        uint32_t al[4][4], bl[4][2];
#pragma unroll
        for (int mt = 0; mt < 4; mt++) {
            const float4 v = *(const float4*)(Ah + (((ks * 8 + (wm * 4 + mt)) * 32 + lsw) << 2));
            af[mt][0] = __float_as_uint(v.x); af[mt][1] = __float_as_uint(v.y);
            af[mt][2] = __float_as_uint(v.z); af[mt][3] = __float_as_uint(v.w);
            if (COMP) {
                const float4 w = *(const float4*)(Al + (((ks * 8 + (wm * 4 + mt)) * 32 + lsw) << 2));
                al[mt][0] = __float_as_uint(w.x); al[mt][1] = __float_as_uint(w.y);
                al[mt][2] = __float_as_uint(w.z); al[mt][3] = __float_as_uint(w.w);
            }
        }
#pragma unroll
        for (int nt = 0; nt < 4; nt++) {
            const float2 v = *(const float2*)(Bh + (((ks * 16 + (wn * 4 + nt)) * 32 + lsw) << 1));
            bf[nt][0] = __float_as_uint(v.x); bf[nt][1] = __float_as_uint(v.y);
            if (COMP) {
                const float2 w = *(const float2*)(Bl + (((ks * 16 + (wn * 4 + nt)) * 32 + lsw) << 1));
                bl[nt][0] = __float_as_uint(w.x); bl[nt][1] = __float_as_uint(w.y);
            }
        }
#pragma unroll
        for (int mt = 0; mt < 4; mt++)
#pragma unroll
            for (int nt = 0; nt < 4; nt++) {
                mma_tf32(acc[mt][nt], af[mt], bf[nt]);
                if (COMP) {
                    mma_tf32(acc[mt][nt], al[mt], bf[nt]);
                    mma_tf32(acc[mt][nt], af[mt], bl[nt]);
                }
            }
    }
}

template<bool COMP>
__global__ void __launch_bounds__(256)
gemm_tf32(const float* __restrict__ A, const float* __restrict__ B,
          float* __restrict__ C, int M, int N, int K,
          const float* __restrict__ bias, int flags) {
    extern __shared__ float smem[];
    constexpr int STG = COMP ? STG_COMP : STG_FAST;
    float* const s0 = smem;          // compile-time offsets from dynamic base
    float* const s1 = smem + STG;

    const int tid  = threadIdx.x;
    const int lane = tid & 31;
    const int warp = tid >> 5;
    const int wm = warp >> 2;     // 0..1
    const int wn = warp & 3;      // 0..3
    const int m0 = blockIdx.x * 128;
    const int n0 = blockIdx.y * 128;

    float acc[4][4][4];
#pragma unroll
    for (int i = 0; i < 4; i++)
#pragma unroll
        for (int j = 0; j < 4; j++)
#pragma unroll
            for (int s = 0; s < 4; s++) acc[i][j][s] = 0.0f;

    const int lrow = tid >> 3;        // 0..31
    const int lk4  = (tid & 7) * 4;   // 0,4,...,28
    const int nK = K >> 5;            // all call sites: nK even (16 or 32)

    float4 pa[4], pb[4];

    // ---- prologue: tile 0 -> stage 0 ----
    load_tile<COMP>(A, B, M, N, K, m0, n0, lk4, lrow, pa, pb);
    store_stage<COMP>(s0, pa, pb, lrow, lk4);
    __syncthreads();

    for (int kt = 0; kt < nK; kt += 2) {
        // -- even tile: compute s0, fill s1 --
        if (kt + 1 < nK)
            load_tile<COMP>(A, B, M, N, K, m0, n0, (kt + 1) * 32 + lk4, lrow, pa, pb);
        compute_stage<COMP>(s0, acc, wm, wn, lane);
        if (kt + 1 < nK) {
            store_stage<COMP>(s1, pa, pb, lrow, lk4);
            __syncthreads();    // s1 ready; everyone done reading s0

            // -- odd tile: compute s1, fill s0 --
            if (kt + 2 < nK)
                load_tile<COMP>(A, B, M, N, K, m0, n0, (kt + 2) * 32 + lk4, lrow, pa, pb);
            compute_stage<COMP>(s1, acc, wm, wn, lane);
            if (kt + 2 < nK) {
                store_stage<COMP>(s0, pa, pb, lrow, lk4);
                __syncthreads();  // s0 ready; everyone done reading s1
            }
        }
    }

    // ---- epilogue ----
    const int row = lane >> 2;          // 0..7
    const int col = (lane & 3) * 2;     // 0,2,4,6
#pragma unroll
    for (int mt = 0; mt < 4; mt++) {
#pragma unroll
        for (int nt = 0; nt < 4; nt++) {
#pragma unroll
            for (int s = 0; s < 4; s++) {
                int gm = m0 + wm * 64 + mt * 16 + row + ((s >> 1) ? 8 : 0);
                int gn = n0 + wn * 32 + nt * 8 + col + (s & 1);
                if (gm >= M || gn >= N) continue;
                float v = acc[mt][nt][s];
                if (flags & 1) v += bias[gn];
                if (flags & 2) v = tanhf(v);
                size_t idx;
                if (flags & 4) {
                    int b = gm & 15;     // gm = t*16 + b
                    int t = gm >> 4;
                    idx = (size_t)(b * TT + t) * (size_t)N + (size_t)gn;
                } else {
                    idx = (size_t)gm * (size_t)N + (size_t)gn;
                }
                C[idx] = v;
            }
        }
    }
}

// ---------------- fused h0 kernel (zero initial state) ----------------
__global__ __launch_bounds__(256)
void gru_h0(const float* __restrict__ Wih, const float* __restrict__ bih,
            const float* __restrict__ bhh,
            const float* __restrict__ x,      // BB x HH
            float* __restrict__ hout) {       // BB x HH
    const int warp = threadIdx.x >> 5;
    const int lane = threadIdx.x & 31;
    const int j = blockIdx.x * 8 + warp;

    float accr[BB], accz[BB], accn[BB];
#pragma unroll
    for (int b = 0; b < BB; b++) { accr[b] = 0.f; accz[b] = 0.f; accn[b] = 0.f; }

    const float4* wr = (const float4*)(Wih + (size_t)j * HH);
    const float4* wz = (const float4*)(Wih + (size_t)(HH + j) * HH);
    const float4* wn = (const float4*)(Wih + (size_t)(2 * HH + j) * HH);
    const float4* x4 = (const float4*)x;

#pragma unroll
    for (int it = 0; it < 8; it++) {
        int k4 = it * 32 + lane;
        float4 a = wr[k4];
        float4 bq = wz[k4];
        float4 c = wn[k4];
#pragma unroll
        for (int b = 0; b < BB; b++) {
            float4 hv = x4[b * 256 + k4];
            accr[b] = fmaf(a.x, hv.x, fmaf(a.y, hv.y, fmaf(a.z, hv.z, fmaf(a.w, hv.w, accr[b]))));
            accz[b] = fmaf(bq.x, hv.x, fmaf(bq.y, hv.y, fmaf(bq.z, hv.z, fmaf(bq.w, hv.w, accz[b]))));
            accn[b] = fmaf(c.x, hv.x, fmaf(c.y, hv.y, fmaf(c.z, hv.z, fmaf(c.w, hv.w, accn[b]))));
        }
    }

    float sr = 0.f, sz = 0.f, sn = 0.f;
#pragma unroll
    for (int b = 0; b < BB; b++) {
        float r = accr[b], z = accz[b], n = accn[b];
#pragma unroll
        for (int off = 16; off > 0; off >>= 1) {
            r += __shfl_xor_sync(0xFFFFFFFFu, r, off);
            z += __shfl_xor_sync(0xFFFFFFFFu, z, off);
            n += __shfl_xor_sync(0xFFFFFFFFu, n, off);
        }
        if (lane == b) { sr = r; sz = z; sn = n; }
    }

    if (lane < BB) {
        float xr = sr + bih[j];
        float xz = sz + bih[HH + j];
        float xn = sn + bih[2 * HH + j];
        float r = 1.f / (1.f + expf(-(xr + bhh[j])));
        float z = 1.f / (1.f + expf(-(xz + bhh[HH + j])));
        float n = tanhf(xn + r * bhh[2 * HH + j]);
        hout[lane * HH + j] = (1.f - z) * n;
    }
}

// ---------------- persistent GRU scan (one layer, all 64 steps) ----------------
// Legacy contended barrier: used once at kernel start to fence the flag reset.
__device__ __forceinline__ void grid_barrier_atomic() {
    __syncthreads();
    if (threadIdx.x == 0) {
        __threadfence();
        unsigned gen = atomicAdd(&g_bar_gen, 0u);
        unsigned arrived = atomicAdd(&g_bar_count, 1u);
        if (arrived == NCTA_SCAN - 1) {
            g_bar_count = 0;
            __threadfence();
            atomicAdd(&g_bar_gen, 1u);
        } else {
            while (atomicAdd(&g_bar_gen, 0u) == gen) { __nanosleep(32); }
        }
    }
    __syncthreads();
}

__global__ void __launch_bounds__(256)
gru_scan(const float* __restrict__ Whh, const float* __restrict__ bhh,
         const float* __restrict__ xp,    // TT x BB x 3H (includes b_ih)
         const float* __restrict__ h0,    // BB x HH
         float* __restrict__ ys) {        // TT x BB x HH
    extern __shared__ float hs[];         // BB*HH floats = 64 KB
    const int tid  = threadIdx.x;
    const int warp = tid >> 5;
    const int lane = tid & 31;
    const int j = blockIdx.x * 8 + warp;  // hidden unit

    // ---- reset own barrier flag; fence with ONE atomic barrier ----
    if (tid == 0) __stcg(&g_arrive2[blockIdx.x], 0u);
    grid_barrier_atomic();   // all flags zeroed & visible before any step-barrier use

    const float4* wr = (const float4*)(Whh + (size_t)j * HH);
    const float4* wz = (const float4*)(Whh + (size_t)(HH + j) * HH);
    const float4* wn = (const float4*)(Whh + (size_t)(2 * HH + j) * HH);
    float4 wcr[8], wcz[8], wcn[8];
#pragma unroll
    for (int it = 0; it < 8; it++) {
        int k4 = it * 32 + lane;
        wcr[it] = wr[k4];
        wcz[it] = wz[k4];
        wcn[it] = wn[k4];
    }
    const float bhr = bhh[j];
    const float bhz = bhh[HH + j];
    const float bhn = bhh[2 * HH + j];

    for (int t = 0; t < TT; t++) {
        const float4* hp4 = (const float4*)((t == 0) ? h0 : (ys + (size_t)(t - 1) * BB * HH));
#pragma unroll 4
        for (int idx = tid; idx < BB * HH / 4; idx += 256)
            ((float4*)hs)[idx] = hp4[idx];
        __syncthreads();

        float accr[BB], accz[BB], accn[BB];
#pragma unroll
        for (int b = 0; b < BB; b++) { accr[b] = 0.f; accz[b] = 0.f; accn[b] = 0.f; }

        const float4* h4 = (const float4*)hs;
#pragma unroll
        for (int it = 0; it < 8; it++) {
            int k4 = it * 32 + lane;
            float4 a = wcr[it], bq = wcz[it], c = wcn[it];
#pragma unroll
            for (int b = 0; b < BB; b++) {
                float4 hv = h4[b * 256 + k4];
                accr[b] = fmaf(a.x, hv.x, fmaf(a.y, hv.y, fmaf(a.z, hv.z, fmaf(a.w, hv.w, accr[b]))));
                accz[b] = fmaf(bq.x, hv.x, fmaf(bq.y, hv.y, fmaf(bq.z, hv.z, fmaf(bq.w, hv.w, accz[b]))));
                accn[b] = fmaf(c.x, hv.x, fmaf(c.y, hv.y, fmaf(c.z, hv.z, fmaf(c.w, hv.w, accn[b]))));
            }
        }

        float sr = 0.f, sz = 0.f, sn = 0.f;
#pragma unroll
        for (int b = 0; b < BB; b++) {
            float r = accr[b], z = accz[b], n = accn[b];
#pragma unroll
            for (int off = 16; off > 0; off >>= 1) {
                r += __shfl_xor_sync(0xFFFFFFFFu, r, off);
                z += __shfl_xor_sync(0xFFFFFFFFu, z, off);
                n += __shfl_xor_sync(0xFFFFFFFFu, n, off);
            }
            if (lane == b) { sr = r; sz = z; sn = n; }
        }

        if (lane < BB) {
            int b = lane;
            const float* xg = xp + (size_t)t * BB * G3H + (size_t)b * G3H;
            float xr = xg[j];
            float xz = xg[HH + j];
            float xn = xg[2 * HH + j];
            float hp = hs[b * HH + j];
            float r = 1.f / (1.f + expf(-(xr + sr + bhr)));
            float z = 1.f / (1.f + expf(-(xz + sz + bhz)));
            float n = tanhf(xn + r * (sn + bhn));
            ys[(size_t)t * BB * HH + b * HH + j] = (1.f - z) * n + z * hp;
        }

        // ---- distributed flag barrier (skip after last step: inter-kernel
        //      stream ordering covers the final visibility) ----
        if (t < TT - 1) {
            __syncthreads();                 // all lanes of CTA done with step t
            const unsigned target = (unsigned)(t + 1);
            if (tid == 0) {
                __threadfence();             // ys writes visible before flag
                __stcg(&g_arrive2[blockIdx.x], target);
            }
            if (tid < NCTA_SCAN) {
                while (__ldcg(&g_arrive2[tid]) < target) { __nanosleep(20); }
            }
            __syncthreads();                 // pollers done -> whole CTA may proceed
            __threadfence();                 // acquire: order subsequent ys reads
        }
    }
}

// ---------------- host orchestration ----------------
#define SMEM_COMP  (2 * STG_COMP * 4)   // 128 KB
#define SMEM_FAST  (2 * STG_FAST * 4)   // 64 KB
#define SMEM_SCAN  (BB * HH * 4)        // 64 KB

extern "C" void kernel_launch(void* const* d_in, const int* in_sizes, int n_in,
                              void* d_out, int out_size) {
    const float* init  = (const float*)d_in[0];
    const int*   helper= (const int*)  d_in[1];
    const float* emb   = (const float*)d_in[2];
    const float* W_ih0 = (const float*)d_in[3];
    const float* W_hh0 = (const float*)d_in[4];
    const float* b_ih0 = (const float*)d_in[5];
    const float* b_hh0 = (const float*)d_in[6];
    const float* W_ih1 = (const float*)d_in[7];
    const float* W_hh1 = (const float*)d_in[8];
    const float* b_ih1 = (const float*)d_in[9];
    const float* b_hh1 = (const float*)d_in[10];
    const float* Wc_w  = (const float*)d_in[11];
    const float* Wc_b  = (const float*)d_in[12];
    float* out = (float*)d_out;

    float *x0, *h0a, *h0b, *xdec, *xp, *ys0, *ys1, *fin;
    cudaGetSymbolAddress((void**)&x0,   g_x0);
    cudaGetSymbolAddress((void**)&h0a,  g_h0a);
    cudaGetSymbolAddress((void**)&h0b,  g_h0b);
    cudaGetSymbolAddress((void**)&xdec, g_xdec);
    cudaGetSymbolAddress((void**)&xp,   g_xp);
    cudaGetSymbolAddress((void**)&ys0,  g_ys0);
    cudaGetSymbolAddress((void**)&ys1,  g_ys1);
    cudaGetSymbolAddress((void**)&fin,  g_final);

    cudaFuncSetAttribute(gemm_tf32<true>,  cudaFuncAttributeMaxDynamicSharedMemorySize, SMEM_COMP);
    cudaFuncSetAttribute(gemm_tf32<false>, cudaFuncAttributeMaxDynamicSharedMemorySize, SMEM_FAST);
    cudaFuncSetAttribute(gru_scan,         cudaFuncAttributeMaxDynamicSharedMemorySize, SMEM_SCAN);

    dim3 blk(256);

    // ---- h0 (fused small path) ----
    build_x0<<<BB, blk>>>(init, x0);
    gru_h0<<<128, blk>>>(W_ih0, b_ih0, b_hh0, x0, h0a);
    gru_h0<<<128, blk>>>(W_ih1, b_ih1, b_hh1, h0a, h0b);

    // ---- decoder inputs ----
    build_xdec<<<TT * BB, blk>>>(helper, emb, init, xdec);

    // ---- layer 0: xp (single-pass tf32) then persistent scan ----
    gemm_tf32<false><<<dim3(TT * BB / 128, G3H / 128), blk, SMEM_FAST>>>(
        xdec, W_ih0, xp, TT * BB, G3H, 2 * EE, b_ih0, 1);
    gru_scan<<<NCTA_SCAN, blk, SMEM_SCAN>>>(W_hh0, b_hh0, xp, h0a, ys0);

    // ---- layer 1: xp (single-pass tf32) then persistent scan ----
    gemm_tf32<false><<<dim3(TT * BB / 128, G3H / 128), blk, SMEM_FAST>>>(
        ys0, W_ih1, xp, TT * BB, G3H, HH, b_ih1, 1);
    gru_scan<<<NCTA_SCAN, blk, SMEM_SCAN>>>(W_hh1, b_hh1, xp, h0b, ys1);

    // ---- final = tanh(ys1 @ Wc_w^T + Wc_b), compensated ----
    gemm_tf32<true><<<dim3(TT * BB / 128, EE / 128), blk, SMEM_COMP>>>(
        ys1, Wc_w, fin, TT * BB, EE, HH, Wc_b, 1 | 2);

    // ---- logits = final @ emb^T, single-pass tf32, stored (B,T,V) ----
    gemm_tf32<false><<<dim3(TT * BB / 128, (VV + 127) / 128), blk, SMEM_FAST>>>(
        fin, emb, out, TT * BB, VV, EE, nullptr, 4);
}

// round 13
// speedup vs baseline: 1.3916x; 1.3916x over previous
#include <cuda_runtime.h>
#include <cuda_bf16.h>
#include <math.h>
#include <stdint.h>

// Problem constants
#define BB 16      // batch
#define TT 64      // seq len
#define VV 50257   // vocab
#define EE 512     // embed
#define HH 1024    // hidden
#define G3H 3072   // 3*H

#define NCTA_SCAN 128   // persistent scan grid (<=148 SMs -> all resident)

// ---------------- scratch (no allocations allowed) ----------------
__device__ float g_x0[BB * 2 * EE];          // 16x1024
__device__ float g_h0a[BB * HH];             // layer0 h0
__device__ float g_h0b[BB * HH];             // layer1 h0
__device__ float g_xdec[TT * BB * 2 * EE];   // 1024x1024
__device__ float g_xp[TT * BB * G3H];        // 1024x3072 (reused for both layers)
__device__ float g_ys0[TT * BB * HH];        // 1024x1024
__device__ float g_ys1[TT * BB * HH];        // 1024x1024
__device__ float g_final[TT * BB * EE];      // 1024x512

// grid-barrier state (self-restoring: count returns to 0; gen compared by equality)
__device__ unsigned g_bar_count = 0;
__device__ unsigned g_bar_gen   = 0;

// ---------------- small builders ----------------
__global__ void build_x0(const float* __restrict__ init, float* __restrict__ x0) {
    int b = blockIdx.x;
    for (int c = threadIdx.x; c < EE; c += blockDim.x) {
        float v = init[b * EE + c];
        x0[b * (2 * EE) + c] = v;
        x0[b * (2 * EE) + EE + c] = v;
    }
}

__global__ void build_xdec(const int* __restrict__ helper,
                           const float* __restrict__ emb,
                           const float* __restrict__ init,
                           float* __restrict__ xdec) {
    int r = blockIdx.x;            // r = t*B + b
    int t = r >> 4;
    int b = r & 15;
    int tok = helper[b * TT + t];
    const float* src0 = emb + (size_t)tok * EE;
    const float* src1 = init + b * EE;
    float* dst = xdec + (size_t)r * (2 * EE);
    for (int c = threadIdx.x; c < EE; c += blockDim.x) {
        dst[c] = src0[c];
        dst[EE + c] = src1[c];
    }
}

// ---------------- tf32 / f32x2 helpers ----------------
__device__ __forceinline__ uint32_t f2tf32(float x) {
    uint32_t r;
    asm("cvt.rna.tf32.f32 %0, %1;" : "=r"(r) : "f"(x));
    return r;
}

__device__ __forceinline__ void mma_tf32(float* c, const uint32_t* a, const uint32_t* b) {
    asm volatile(
        "mma.sync.aligned.m16n8k8.row.col.f32.tf32.tf32.f32 "
        "{%0,%1,%2,%3}, {%4,%5,%6,%7}, {%8,%9}, {%0,%1,%2,%3};"
        : "+f"(c[0]), "+f"(c[1]), "+f"(c[2]), "+f"(c[3])
        : "r"(a[0]), "r"(a[1]), "r"(a[2]), "r"(a[3]), "r"(b[0]), "r"(b[1]));
}

// packed fp32x2 FMA (sm_100+; PTX-only, ptxas never auto-fuses)
__device__ __forceinline__ void fma2(unsigned long long& d,
                                     unsigned long long a, unsigned long long b) {
    asm("fma.rn.f32x2 %0, %1, %2, %3;" : "=l"(d) : "l"(a), "l"(b), "l"(d));
}
__device__ __forceinline__ float f32x2_sum(unsigned long long v) {
    float lo, hi;
    asm("mov.b64 {%0,%1}, %2;" : "=f"(lo), "=f"(hi) : "l"(v));
    return lo + hi;
}

// ---------------- tensor-core GEMM: C = A(MxK) * B(NxK)^T ----------------
// Block tile 128x128, K tile 32. 8 warps: warp (wm,wn) owns 64x32.
// Grid: blockIdx.x = M-tile (FAST axis), blockIdx.y = N-tile (B-tile L2 reuse).
// Double-buffered with compile-time stage offsets; one __syncthreads per K-tile.
// ks-XOR bank swizzle on fragment rows (STS conflict 4 -> 1).
// flags: bit0 = add bias[n]; bit1 = tanh; bit2 = (b,t) transposed store (logits)
// COMP: compensated tf32 split (Ah*Bh + Al*Bh + Ah*Bl) ~ fp32 accuracy.

#define STG_FAST 8192    // floats per stage: Ah(4096)+Bh(4096)
#define STG_COMP 16384   // + Al(4096)+Bl(4096)

template<bool COMP>
__device__ __forceinline__ void load_tile(
    const float* __restrict__ A, const float* __restrict__ B,
    int M, int N, int K, int m0, int n0, int kbase, int lrow,
    float4* pa, float4* pb) {
#pragma unroll
    for (int p = 0; p < 4; p++) {
        int gr = m0 + lrow + p * 32;
        pa[p] = (gr < M) ? *(const float4*)&A[(size_t)gr * K + kbase]
                         : make_float4(0.f, 0.f, 0.f, 0.f);
        int gn = n0 + lrow + p * 32;
        pb[p] = (gn < N) ? *(const float4*)&B[(size_t)gn * K + kbase]
                         : make_float4(0.f, 0.f, 0.f, 0.f);
    }
}

template<bool COMP>
__device__ __forceinline__ void store_stage(
    float* stage, const float4* pa, const float4* pb, int lrow, int lk4) {
    float* Ah = stage;
    float* Bh = stage + 4096;
    float* Al = COMP ? (stage + 8192)  : nullptr;
    float* Bl = COMP ? (stage + 12288) : nullptr;
#pragma unroll
    for (int p = 0; p < 4; p++) {
        int m = lrow + p * 32;
        const float* av = (const float*)&pa[p];
        const float* bv = (const float*)&pb[p];
#pragma unroll
        for (int i = 0; i < 4; i++) {
            int k = lk4 + i;
            int ks = k >> 3, kc = k & 7;
            {
                int mt = m >> 4, r = m & 15;
                int ln = (((r & 7) << 2) | (kc & 3)) ^ ks;
                int slot = (r >> 3) | ((kc >> 2) << 1);
                int idx = (((ks * 8 + mt) * 32 + ln) << 2) | slot;
                float x = av[i];
                uint32_t hb = f2tf32(x);
                Ah[idx] = __uint_as_float(hb);
                if (COMP) Al[idx] = __uint_as_float(f2tf32(x - __uint_as_float(hb)));
            }
            {
                int nt = m >> 3;
                int ln = (((m & 7) << 2) | (kc & 3)) ^ ks;
                int slot = kc >> 2;
                int idx = (((ks * 16 + nt) * 32 + ln) << 1) | slot;
                float x = bv[i];
                uint32_t hb = f2tf32(x);
                Bh[idx] = __uint_as_float(hb);
                if (COMP) Bl[idx] = __uint_as_float(f2tf32(x - __uint_as_float(hb)));
            }
        }
    }
}

template<bool COMP>
__device__ __forceinline__ void compute_stage(
    const float* stage, float acc[4][4][4], int wm, int wn, int lane) {
    const float* Ah = stage;
    const float* Bh = stage + 4096;
    const float* Al = COMP ? (stage + 8192)  : nullptr;
    const float* Bl = COMP ? (stage + 12288) : nullptr;
#pragma unroll
    for (int ks = 0; ks < 4; ks++) {
        const int lsw = lane ^ ks;
        uint32_t af[4][4], bf[4][2];
        uint32_t al[4][4], bl[4][2];
#pragma unroll
        for (int mt = 0; mt < 4; mt++) {
            const float4 v = *(const float4*)(Ah + (((ks * 8 + (wm * 4 + mt)) * 32 + lsw) << 2));
            af[mt][0] = __float_as_uint(v.x); af[mt][1] = __float_as_uint(v.y);
            af[mt][2] = __float_as_uint(v.z); af[mt][3] = __float_as_uint(v.w);
            if (COMP) {
                const float4 w = *(const float4*)(Al + (((ks * 8 + (wm * 4 + mt)) * 32 + lsw) << 2));
                al[mt][0] = __float_as_uint(w.x); al[mt][1] = __float_as_uint(w.y);
                al[mt][2] = __float_as_uint(w.z); al[mt][3] = __float_as_uint(w.w);
            }
        }
#pragma unroll
        for (int nt = 0; nt < 4; nt++) {
            const float2 v = *(const float2*)(Bh + (((ks * 16 + (wn * 4 + nt)) * 32 + lsw) << 1));
            bf[nt][0] = __float_as_uint(v.x); bf[nt][1] = __float_as_uint(v.y);
            if (COMP) {
                const float2 w = *(const float2*)(Bl + (((ks * 16 + (wn * 4 + nt)) * 32 + lsw) << 1));
                bl[nt][0] = __float_as_uint(w.x); bl[nt][1] = __float_as_uint(w.y);
            }
        }
#pragma unroll
        for (int mt = 0; mt < 4; mt++)
#pragma unroll
            for (int nt = 0; nt < 4; nt++) {
                mma_tf32(acc[mt][nt], af[mt], bf[nt]);
                if (COMP) {
                    mma_tf32(acc[mt][nt], al[mt], bf[nt]);
                    mma_tf32(acc[mt][nt], af[mt], bl[nt]);
                }
            }
    }
}

template<bool COMP>
__global__ void __launch_bounds__(256)
gemm_tf32(const float* __restrict__ A, const float* __restrict__ B,
          float* __restrict__ C, int M, int N, int K,
          const float* __restrict__ bias, int flags) {
    extern __shared__ float smem[];
    constexpr int STG = COMP ? STG_COMP : STG_FAST;
    float* const s0 = smem;          // compile-time offsets from dynamic base
    float* const s1 = smem + STG;

    const int tid  = threadIdx.x;
    const int lane = tid & 31;
    const int warp = tid >> 5;
    const int wm = warp >> 2;     // 0..1
    const int wn = warp & 3;      // 0..3
    const int m0 = blockIdx.x * 128;
    const int n0 = blockIdx.y * 128;

    float acc[4][4][4];
#pragma unroll
    for (int i = 0; i < 4; i++)
#pragma unroll
        for (int j = 0; j < 4; j++)
#pragma unroll
            for (int s = 0; s < 4; s++) acc[i][j][s] = 0.0f;

    const int lrow = tid >> 3;        // 0..31
    const int lk4  = (tid & 7) * 4;   // 0,4,...,28
    const int nK = K >> 5;            // all call sites: nK even (16 or 32)

    float4 pa[4], pb[4];

    // ---- prologue: tile 0 -> stage 0 ----
    load_tile<COMP>(A, B, M, N, K, m0, n0, lk4, lrow, pa, pb);
    store_stage<COMP>(s0, pa, pb, lrow, lk4);
    __syncthreads();

    for (int kt = 0; kt < nK; kt += 2) {
        // -- even tile: compute s0, fill s1 --
        if (kt + 1 < nK)
            load_tile<COMP>(A, B, M, N, K, m0, n0, (kt + 1) * 32 + lk4, lrow, pa, pb);
        compute_stage<COMP>(s0, acc, wm, wn, lane);
        if (kt + 1 < nK) {
            store_stage<COMP>(s1, pa, pb, lrow, lk4);
            __syncthreads();    // s1 ready; everyone done reading s0

            // -- odd tile: compute s1, fill s0 --
            if (kt + 2 < nK)
                load_tile<COMP>(A, B, M, N, K, m0, n0, (kt + 2) * 32 + lk4, lrow, pa, pb);
            compute_stage<COMP>(s1, acc, wm, wn, lane);
            if (kt + 2 < nK) {
                store_stage<COMP>(s0, pa, pb, lrow, lk4);
                __syncthreads();  // s0 ready; everyone done reading s1
            }
        }
    }

    // ---- epilogue ----
    const int row = lane >> 2;          // 0..7
    const int col = (lane & 3) * 2;     // 0,2,4,6
#pragma unroll
    for (int mt = 0; mt < 4; mt++) {
#pragma unroll
        for (int nt = 0; nt < 4; nt++) {
#pragma unroll
            for (int s = 0; s < 4; s++) {
                int gm = m0 + wm * 64 + mt * 16 + row + ((s >> 1) ? 8 : 0);
                int gn = n0 + wn * 32 + nt * 8 + col + (s & 1);
                if (gm >= M || gn >= N) continue;
                float v = acc[mt][nt][s];
                if (flags & 1) v += bias[gn];
                if (flags & 2) v = tanhf(v);
                size_t idx;
                if (flags & 4) {
                    int b = gm & 15;     // gm = t*16 + b
                    int t = gm >> 4;
                    idx = (size_t)(b * TT + t) * (size_t)N + (size_t)gn;
                } else {
                    idx = (size_t)gm * (size_t)N + (size_t)gn;
                }
                C[idx] = v;
            }
        }
    }
}

// ---------------- fused h0 kernel (zero initial state) ----------------
__global__ __launch_bounds__(256)
void gru_h0(const float* __restrict__ Wih, const float* __restrict__ bih,
            const float* __restrict__ bhh,
            const float* __restrict__ x,      // BB x HH
            float* __restrict__ hout) {       // BB x HH
    const int warp = threadIdx.x >> 5;
    const int lane = threadIdx.x & 31;
    const int j = blockIdx.x * 8 + warp;

    float accr[BB], accz[BB], accn[BB];
#pragma unroll
    for (int b = 0; b < BB; b++) { accr[b] = 0.f; accz[b] = 0.f; accn[b] = 0.f; }

    const float4* wr = (const float4*)(Wih + (size_t)j * HH);
    const float4* wz = (const float4*)(Wih + (size_t)(HH + j) * HH);
    const float4* wn = (const float4*)(Wih + (size_t)(2 * HH + j) * HH);
    const float4* x4 = (const float4*)x;

#pragma unroll
    for (int it = 0; it < 8; it++) {
        int k4 = it * 32 + lane;
        float4 a = wr[k4];
        float4 bq = wz[k4];
        float4 c = wn[k4];
#pragma unroll
        for (int b = 0; b < BB; b++) {
            float4 hv = x4[b * 256 + k4];
            accr[b] = fmaf(a.x, hv.x, fmaf(a.y, hv.y, fmaf(a.z, hv.z, fmaf(a.w, hv.w, accr[b]))));
            accz[b] = fmaf(bq.x, hv.x, fmaf(bq.y, hv.y, fmaf(bq.z, hv.z, fmaf(bq.w, hv.w, accz[b]))));
            accn[b] = fmaf(c.x, hv.x, fmaf(c.y, hv.y, fmaf(c.z, hv.z, fmaf(c.w, hv.w, accn[b]))));
        }
    }

    float sr = 0.f, sz = 0.f, sn = 0.f;
#pragma unroll
    for (int b = 0; b < BB; b++) {
        float r = accr[b], z = accz[b], n = accn[b];
#pragma unroll
        for (int off = 16; off > 0; off >>= 1) {
            r += __shfl_xor_sync(0xFFFFFFFFu, r, off);
            z += __shfl_xor_sync(0xFFFFFFFFu, z, off);
            n += __shfl_xor_sync(0xFFFFFFFFu, n, off);
        }
        if (lane == b) { sr = r; sz = z; sn = n; }
    }

    if (lane < BB) {
        float xr = sr + bih[j];
        float xz = sz + bih[HH + j];
        float xn = sn + bih[2 * HH + j];
        float r = 1.f / (1.f + expf(-(xr + bhh[j])));
        float z = 1.f / (1.f + expf(-(xz + bhh[HH + j])));
        float n = tanhf(xn + r * bhh[2 * HH + j]);
        hout[lane * HH + j] = (1.f - z) * n;
    }
}

// ---------------- persistent GRU scan (one layer, all 64 steps) ----------------
__device__ __forceinline__ void grid_barrier() {
    __syncthreads();
    if (threadIdx.x == 0) {
        __threadfence();
        unsigned gen = atomicAdd(&g_bar_gen, 0u);     // read gen BEFORE arriving
        unsigned arrived = atomicAdd(&g_bar_count, 1u);
        if (arrived == NCTA_SCAN - 1) {
            g_bar_count = 0;
            __threadfence();
            atomicAdd(&g_bar_gen, 1u);
        } else {
            while (atomicAdd(&g_bar_gen, 0u) == gen) { __nanosleep(32); }
        }
    }
    __syncthreads();
}

__global__ void __launch_bounds__(256)
gru_scan(const float* __restrict__ Whh, const float* __restrict__ bhh,
         const float* __restrict__ xp,    // TT x BB x 3H (includes b_ih)
         const float* __restrict__ h0,    // BB x HH
         float* __restrict__ ys) {        // TT x BB x HH
    extern __shared__ float hs[];         // BB*HH floats = 64 KB
    const int tid  = threadIdx.x;
    const int warp = tid >> 5;
    const int lane = tid & 31;
    const int j = blockIdx.x * 8 + warp;  // hidden unit

    // register-cache the 3 Whh rows for unit j as packed f32x2 pairs
    const int k4 = 0;  // silence unused warnings pattern
    (void)k4;
    const ulonglong2* wr2 = (const ulonglong2*)(Whh + (size_t)j * HH);
    const ulonglong2* wz2 = (const ulonglong2*)(Whh + (size_t)(HH + j) * HH);
    const ulonglong2* wn2 = (const ulonglong2*)(Whh + (size_t)(2 * HH + j) * HH);
    ulonglong2 wcr[8], wcz[8], wcn[8];
#pragma unroll
    for (int it = 0; it < 8; it++) {
        int idx = it * 32 + lane;        // 16-byte units
        wcr[it] = wr2[idx];
        wcz[it] = wz2[idx];
        wcn[it] = wn2[idx];
    }
    const float bhr = bhh[j];
    const float bhz = bhh[HH + j];
    const float bhn = bhh[2 * HH + j];

    for (int t = 0; t < TT; t++) {
        // stage h_prev into smem
        const float4* hp4 = (const float4*)((t == 0) ? h0 : (ys + (size_t)(t - 1) * BB * HH));
#pragma unroll 4
        for (int idx = tid; idx < BB * HH / 4; idx += 256)
            ((float4*)hs)[idx] = hp4[idx];
        __syncthreads();

        // packed f32x2 accumulators (even/odd k interleaved; summed at the end)
        unsigned long long ar[BB], az[BB], an[BB];
#pragma unroll
        for (int b = 0; b < BB; b++) { ar[b] = 0ull; az[b] = 0ull; an[b] = 0ull; }

        const ulonglong2* h2 = (const ulonglong2*)hs;   // 16-byte units
#pragma unroll
        for (int it = 0; it < 8; it++) {
            int idx = it * 32 + lane;
            ulonglong2 a = wcr[it], bq = wcz[it], c = wcn[it];
#pragma unroll
            for (int b = 0; b < BB; b++) {
                ulonglong2 hv = h2[b * 256 + idx];
                fma2(ar[b], a.x,  hv.x); fma2(ar[b], a.y,  hv.y);
                fma2(az[b], bq.x, hv.x); fma2(az[b], bq.y, hv.y);
                fma2(an[b], c.x,  hv.x); fma2(an[b], c.y,  hv.y);
            }
        }

        float sr = 0.f, sz = 0.f, sn = 0.f;
#pragma unroll
        for (int b = 0; b < BB; b++) {
            float r = f32x2_sum(ar[b]);
            float z = f32x2_sum(az[b]);
            float n = f32x2_sum(an[b]);
#pragma unroll
            for (int off = 16; off > 0; off >>= 1) {
                r += __shfl_xor_sync(0xFFFFFFFFu, r, off);
                z += __shfl_xor_sync(0xFFFFFFFFu, z, off);
                n += __shfl_xor_sync(0xFFFFFFFFu, n, off);
            }
            if (lane == b) { sr = r; sz = z; sn = n; }
        }

        if (lane < BB) {
            int b = lane;
            const float* xg = xp + (size_t)t * BB * G3H + (size_t)b * G3H;
            float xr = xg[j];
            float xz = xg[HH + j];
            float xn = xg[2 * HH + j];
            float hp = hs[b * HH + j];
            float r = 1.f / (1.f + expf(-(xr + sr + bhr)));
            float z = 1.f / (1.f + expf(-(xz + sz + bhz)));
            float n = tanhf(xn + r * (sn + bhn));
            ys[(size_t)t * BB * HH + b * HH + j] = (1.f - z) * n + z * hp;
        }

        if (t < TT - 1)
            grid_barrier();   // writes of step t visible before step t+1 staging
        // after the last step, inter-kernel stream ordering provides visibility
    }
}

// ---------------- host orchestration ----------------
#define SMEM_COMP  (2 * STG_COMP * 4)   // 128 KB
#define SMEM_FAST  (2 * STG_FAST * 4)   // 64 KB
#define SMEM_SCAN  (BB * HH * 4)        // 64 KB

extern "C" void kernel_launch(void* const* d_in, const int* in_sizes, int n_in,
                              void* d_out, int out_size) {
    const float* init  = (const float*)d_in[0];
    const int*   helper= (const int*)  d_in[1];
    const float* emb   = (const float*)d_in[2];
    const float* W_ih0 = (const float*)d_in[3];
    const float* W_hh0 = (const float*)d_in[4];
    const float* b_ih0 = (const float*)d_in[5];
    const float* b_hh0 = (const float*)d_in[6];
    const float* W_ih1 = (const float*)d_in[7];
    const float* W_hh1 = (const float*)d_in[8];
    const float* b_ih1 = (const float*)d_in[9];
    const float* b_hh1 = (const float*)d_in[10];
    const float* Wc_w  = (const float*)d_in[11];
    const float* Wc_b  = (const float*)d_in[12];
    float* out = (float*)d_out;

    float *x0, *h0a, *h0b, *xdec, *xp, *ys0, *ys1, *fin;
    cudaGetSymbolAddress((void**)&x0,   g_x0);
    cudaGetSymbolAddress((void**)&h0a,  g_h0a);
    cudaGetSymbolAddress((void**)&h0b,  g_h0b);
    cudaGetSymbolAddress((void**)&xdec, g_xdec);
    cudaGetSymbolAddress((void**)&xp,   g_xp);
    cudaGetSymbolAddress((void**)&ys0,  g_ys0);
    cudaGetSymbolAddress((void**)&ys1,  g_ys1);
    cudaGetSymbolAddress((void**)&fin,  g_final);

    cudaFuncSetAttribute(gemm_tf32<true>,  cudaFuncAttributeMaxDynamicSharedMemorySize, SMEM_COMP);
    cudaFuncSetAttribute(gemm_tf32<false>, cudaFuncAttributeMaxDynamicSharedMemorySize, SMEM_FAST);
    cudaFuncSetAttribute(gru_scan,         cudaFuncAttributeMaxDynamicSharedMemorySize, SMEM_SCAN);

    dim3 blk(256);

    // ---- h0 (fused small path) ----
    build_x0<<<BB, blk>>>(init, x0);
    gru_h0<<<128, blk>>>(W_ih0, b_ih0, b_hh0, x0, h0a);
    gru_h0<<<128, blk>>>(W_ih1, b_ih1, b_hh1, h0a, h0b);

    // ---- decoder inputs ----
    build_xdec<<<TT * BB, blk>>>(helper, emb, init, xdec);

    // ---- layer 0: xp (single-pass tf32) then persistent scan ----
    gemm_tf32<false><<<dim3(TT * BB / 128, G3H / 128), blk, SMEM_FAST>>>(
        xdec, W_ih0, xp, TT * BB, G3H, 2 * EE, b_ih0, 1);
    gru_scan<<<NCTA_SCAN, blk, SMEM_SCAN>>>(W_hh0, b_hh0, xp, h0a, ys0);

    // ---- layer 1: xp (single-pass tf32) then persistent scan ----
    gemm_tf32<false><<<dim3(TT * BB / 128, G3H / 128), blk, SMEM_FAST>>>(
        ys0, W_ih1, xp, TT * BB, G3H, HH, b_ih1, 1);
    gru_scan<<<NCTA_SCAN, blk, SMEM_SCAN>>>(W_hh1, b_hh1, xp, h0b, ys1);

    // ---- final = tanh(ys1 @ Wc_w^T + Wc_b), compensated ----
    gemm_tf32<true><<<dim3(TT * BB / 128, EE / 128), blk, SMEM_COMP>>>(
        ys1, Wc_w, fin, TT * BB, EE, HH, Wc_b, 1 | 2);

    // ---- logits = final @ emb^T, single-pass tf32, stored (B,T,V) ----
    gemm_tf32<false><<<dim3(TT * BB / 128, (VV + 127) / 128), blk, SMEM_FAST>>>(
        fin, emb, out, TT * BB, VV, EE, nullptr, 4);
}

// round 15
// speedup vs baseline: 1.4469x; 1.0397x over previous
#include <cuda_runtime.h>
#include <cuda_bf16.h>
#include <math.h>
#include <stdint.h>

// Problem constants
#define BB 16      // batch
#define TT 64      // seq len
#define VV 50257   // vocab
#define EE 512     // embed
#define HH 1024    // hidden
#define G3H 3072   // 3*H

#define NCTA_SCAN 128   // persistent scan grid (<=148 SMs -> all resident)

// ---------------- scratch (no allocations allowed) ----------------
__device__ float g_x0[BB * 2 * EE];          // 16x1024
__device__ float g_h0a[BB * HH];             // layer0 h0
__device__ float g_h0b[BB * HH];             // layer1 h0
__device__ float g_xdec[TT * BB * 2 * EE];   // 1024x1024
__device__ float g_xp[TT * BB * G3H];        // 1024x3072 (reused for both layers)
__device__ float g_ys0[TT * BB * HH];        // 1024x1024
__device__ float g_ys1[TT * BB * HH];        // 1024x1024
__device__ float g_final[TT * BB * EE];      // 1024x512

// grid-barrier state (self-restoring: count returns to 0; gen compared by equality)
__device__ unsigned g_bar_count = 0;
__device__ unsigned g_bar_gen   = 0;

// ---------------- small builders ----------------
__global__ void build_x0(const float* __restrict__ init, float* __restrict__ x0) {
    int b = blockIdx.x;
    for (int c = threadIdx.x; c < EE; c += blockDim.x) {
        float v = init[b * EE + c];
        x0[b * (2 * EE) + c] = v;
        x0[b * (2 * EE) + EE + c] = v;
    }
}

__global__ void build_xdec(const int* __restrict__ helper,
                           const float* __restrict__ emb,
                           const float* __restrict__ init,
                           float* __restrict__ xdec) {
    int r = blockIdx.x;            // r = t*B + b
    int t = r >> 4;
    int b = r & 15;
    int tok = helper[b * TT + t];
    const float* src0 = emb + (size_t)tok * EE;
    const float* src1 = init + b * EE;
    float* dst = xdec + (size_t)r * (2 * EE);
    for (int c = threadIdx.x; c < EE; c += blockDim.x) {
        dst[c] = src0[c];
        dst[EE + c] = src1[c];
    }
}

// ---------------- tf32 / f32x2 helpers ----------------
__device__ __forceinline__ uint32_t f2tf32(float x) {
    uint32_t r;
    asm("cvt.rna.tf32.f32 %0, %1;" : "=r"(r) : "f"(x));
    return r;
}

__device__ __forceinline__ void mma_tf32(float* c, const uint32_t* a, const uint32_t* b) {
    asm volatile(
        "mma.sync.aligned.m16n8k8.row.col.f32.tf32.tf32.f32 "
        "{%0,%1,%2,%3}, {%4,%5,%6,%7}, {%8,%9}, {%0,%1,%2,%3};"
        : "+f"(c[0]), "+f"(c[1]), "+f"(c[2]), "+f"(c[3])
        : "r"(a[0]), "r"(a[1]), "r"(a[2]), "r"(a[3]), "r"(b[0]), "r"(b[1]));
}

// packed fp32x2 FMA (sm_100+; PTX-only, ptxas never auto-fuses)
__device__ __forceinline__ void fma2(unsigned long long& d,
                                     unsigned long long a, unsigned long long b) {
    asm("fma.rn.f32x2 %0, %1, %2, %3;" : "=l"(d) : "l"(a), "l"(b), "l"(d));
}
__device__ __forceinline__ float f32x2_sum(unsigned long long v) {
    float lo, hi;
    asm("mov.b64 {%0,%1}, %2;" : "=f"(lo), "=f"(hi) : "l"(v));
    return lo + hi;
}

// =======================================================================
// 64x128 non-COMP GEMM (xp + logits): C = A(MxK) * B(NxK)^T
// Block tile 64(M) x 128(N), K tile 32. 8 warps as 2(m) x 4(n), warp 32x32.
// NO launch_bounds min-blocks (round-3 lesson): acc=32 regs, ~110 total ->
// ptxas reaches 2 CTAs/SM naturally; co-resident CTA hides repack/sync.
// Double-buffered compile-time stages, ks-XOR swizzle, grid x=M (fast).
// flags: bit0 = add bias[n]; bit2 = (b,t) transposed store (logits)
// =======================================================================
#define STG64 6144   // floats per stage: A(2048)+B(4096)

__device__ __forceinline__ void load_tile64(
    const float* __restrict__ A, const float* __restrict__ B,
    int M, int N, int K, int m0, int n0, int kbase, int lrow,
    float4* pa, float4* pb) {
#pragma unroll
    for (int p = 0; p < 2; p++) {
        int gr = m0 + lrow + p * 32;
        pa[p] = (gr < M) ? *(const float4*)&A[(size_t)gr * K + kbase]
                         : make_float4(0.f, 0.f, 0.f, 0.f);
    }
#pragma unroll
    for (int p = 0; p < 4; p++) {
        int gn = n0 + lrow + p * 32;
        pb[p] = (gn < N) ? *(const float4*)&B[(size_t)gn * K + kbase]
                         : make_float4(0.f, 0.f, 0.f, 0.f);
    }
}

__device__ __forceinline__ void store_stage64(
    float* stage, const float4* pa, const float4* pb, int lrow, int lk4) {
    float* Ah = stage;            // [ks4][mt4][ln32][slot4] = 2048
    float* Bh = stage + 2048;     // [ks4][nt16][ln32][slot2] = 4096
#pragma unroll
    for (int p = 0; p < 2; p++) {
        int m = lrow + p * 32;
        const float* av = (const float*)&pa[p];
#pragma unroll
        for (int i = 0; i < 4; i++) {
            int k = lk4 + i;
            int ks = k >> 3, kc = k & 7;
            int mt = m >> 4, r = m & 15;
            int ln = (((r & 7) << 2) | (kc & 3)) ^ ks;
            int slot = (r >> 3) | ((kc >> 2) << 1);
            int idx = (((ks * 4 + mt) * 32 + ln) << 2) | slot;
            Ah[idx] = __uint_as_float(f2tf32(av[i]));
        }
    }
#pragma unroll
    for (int p = 0; p < 4; p++) {
        int n = lrow + p * 32;
        const float* bv = (const float*)&pb[p];
#pragma unroll
        for (int i = 0; i < 4; i++) {
            int k = lk4 + i;
            int ks = k >> 3, kc = k & 7;
            int nt = n >> 3;
            int ln = (((n & 7) << 2) | (kc & 3)) ^ ks;
            int slot = kc >> 2;
            int idx = (((ks * 16 + nt) * 32 + ln) << 1) | slot;
            Bh[idx] = __uint_as_float(f2tf32(bv[i]));
        }
    }
}

__device__ __forceinline__ void compute_stage64(
    const float* stage, float acc[2][4][4], int wm, int wn, int lane) {
    const float* Ah = stage;
    const float* Bh = stage + 2048;
#pragma unroll
    for (int ks = 0; ks < 4; ks++) {
        const int lsw = lane ^ ks;
        uint32_t af[2][4], bf[4][2];
#pragma unroll
        for (int mt = 0; mt < 2; mt++) {
            const float4 v = *(const float4*)(Ah + (((ks * 4 + (wm * 2 + mt)) * 32 + lsw) << 2));
            af[mt][0] = __float_as_uint(v.x); af[mt][1] = __float_as_uint(v.y);
            af[mt][2] = __float_as_uint(v.z); af[mt][3] = __float_as_uint(v.w);
        }
#pragma unroll
        for (int nt = 0; nt < 4; nt++) {
            const float2 v = *(const float2*)(Bh + (((ks * 16 + (wn * 4 + nt)) * 32 + lsw) << 1));
            bf[nt][0] = __float_as_uint(v.x); bf[nt][1] = __float_as_uint(v.y);
        }
#pragma unroll
        for (int mt = 0; mt < 2; mt++)
#pragma unroll
            for (int nt = 0; nt < 4; nt++)
                mma_tf32(acc[mt][nt], af[mt], bf[nt]);
    }
}

__global__ void __launch_bounds__(256)
gemm64(const float* __restrict__ A, const float* __restrict__ B,
       float* __restrict__ C, int M, int N, int K,
       const float* __restrict__ bias, int flags) {
    extern __shared__ float smemf[];
    float* const s0 = smemf;
    float* const s1 = smemf + STG64;

    const int tid  = threadIdx.x;
    const int lane = tid & 31;
    const int warp = tid >> 5;
    const int wm = warp >> 2;     // 0..1
    const int wn = warp & 3;      // 0..3
    const int m0 = blockIdx.x * 64;
    const int n0 = blockIdx.y * 128;

    float acc[2][4][4];
#pragma unroll
    for (int i = 0; i < 2; i++)
#pragma unroll
        for (int j = 0; j < 4; j++)
#pragma unroll
            for (int s = 0; s < 4; s++) acc[i][j][s] = 0.0f;

    const int lrow = tid >> 3;        // 0..31
    const int lk4  = (tid & 7) * 4;   // 0,4,...,28
    const int nK = K >> 5;            // even at all call sites

    float4 pa[2], pb[4];

    load_tile64(A, B, M, N, K, m0, n0, lk4, lrow, pa, pb);
    store_stage64(s0, pa, pb, lrow, lk4);
    __syncthreads();

    for (int kt = 0; kt < nK; kt += 2) {
        if (kt + 1 < nK)
            load_tile64(A, B, M, N, K, m0, n0, (kt + 1) * 32 + lk4, lrow, pa, pb);
        compute_stage64(s0, acc, wm, wn, lane);
        if (kt + 1 < nK) {
            store_stage64(s1, pa, pb, lrow, lk4);
            __syncthreads();

            if (kt + 2 < nK)
                load_tile64(A, B, M, N, K, m0, n0, (kt + 2) * 32 + lk4, lrow, pa, pb);
            compute_stage64(s1, acc, wm, wn, lane);
            if (kt + 2 < nK) {
                store_stage64(s0, pa, pb, lrow, lk4);
                __syncthreads();
            }
        }
    }

    const int row = lane >> 2;
    const int col = (lane & 3) * 2;
#pragma unroll
    for (int mt = 0; mt < 2; mt++) {
#pragma unroll
        for (int nt = 0; nt < 4; nt++) {
#pragma unroll
            for (int s = 0; s < 4; s++) {
                int gm = m0 + (wm * 2 + mt) * 16 + row + ((s >> 1) ? 8 : 0);
                int gn = n0 + (wn * 4 + nt) * 8 + col + (s & 1);
                if (gm >= M || gn >= N) continue;
                float v = acc[mt][nt][s];
                if (flags & 1) v += bias[gn];
                size_t idx;
                if (flags & 4) {
                    int b = gm & 15;     // gm = t*16 + b
                    int t = gm >> 4;
                    idx = (size_t)(b * TT + t) * (size_t)N + (size_t)gn;
                } else {
                    idx = (size_t)gm * (size_t)N + (size_t)gn;
                }
                C[idx] = v;
            }
        }
    }
}

// ---------------- 128x128 COMP GEMM (final projection only) ----------------
#define STG_COMP 16384

__device__ __forceinline__ void load_tile128(
    const float* __restrict__ A, const float* __restrict__ B,
    int M, int N, int K, int m0, int n0, int kbase, int lrow,
    float4* pa, float4* pb) {
#pragma unroll
    for (int p = 0; p < 4; p++) {
        int gr = m0 + lrow + p * 32;
        pa[p] = (gr < M) ? *(const float4*)&A[(size_t)gr * K + kbase]
                         : make_float4(0.f, 0.f, 0.f, 0.f);
        int gn = n0 + lrow + p * 32;
        pb[p] = (gn < N) ? *(const float4*)&B[(size_t)gn * K + kbase]
                         : make_float4(0.f, 0.f, 0.f, 0.f);
    }
}

__device__ __forceinline__ void store_stage128(
    float* stage, const float4* pa, const float4* pb, int lrow, int lk4) {
    float* Ah = stage;
    float* Bh = stage + 4096;
    float* Al = stage + 8192;
    float* Bl = stage + 12288;
#pragma unroll
    for (int p = 0; p < 4; p++) {
        int m = lrow + p * 32;
        const float* av = (const float*)&pa[p];
        const float* bv = (const float*)&pb[p];
#pragma unroll
        for (int i = 0; i < 4; i++) {
            int k = lk4 + i;
            int ks = k >> 3, kc = k & 7;
            {
                int mt = m >> 4, r = m & 15;
                int ln = (((r & 7) << 2) | (kc & 3)) ^ ks;
                int slot = (r >> 3) | ((kc >> 2) << 1);
                int idx = (((ks * 8 + mt) * 32 + ln) << 2) | slot;
                float x = av[i];
                uint32_t hb = f2tf32(x);
                Ah[idx] = __uint_as_float(hb);
                Al[idx] = __uint_as_float(f2tf32(x - __uint_as_float(hb)));
            }
            {
                int nt = m >> 3;
                int ln = (((m & 7) << 2) | (kc & 3)) ^ ks;
                int slot = kc >> 2;
                int idx = (((ks * 16 + nt) * 32 + ln) << 1) | slot;
                float x = bv[i];
                uint32_t hb = f2tf32(x);
                Bh[idx] = __uint_as_float(hb);
                Bl[idx] = __uint_as_float(f2tf32(x - __uint_as_float(hb)));
            }
        }
    }
}

__device__ __forceinline__ void compute_stage128(
    const float* stage, float acc[4][4][4], int wm, int wn, int lane) {
    const float* Ah = stage;
    const float* Bh = stage + 4096;
    const float* Al = stage + 8192;
    const float* Bl = stage + 12288;
#pragma unroll
    for (int ks = 0; ks < 4; ks++) {
        const int lsw = lane ^ ks;
        uint32_t af[4][4], bf[4][2];
        uint32_t al[4][4], bl[4][2];
#pragma unroll
        for (int mt = 0; mt < 4; mt++) {
            const float4 v = *(const float4*)(Ah + (((ks * 8 + (wm * 4 + mt)) * 32 + lsw) << 2));
            af[mt][0] = __float_as_uint(v.x); af[mt][1] = __float_as_uint(v.y);
            af[mt][2] = __float_as_uint(v.z); af[mt][3] = __float_as_uint(v.w);
            const float4 w = *(const float4*)(Al + (((ks * 8 + (wm * 4 + mt)) * 32 + lsw) << 2));
            al[mt][0] = __float_as_uint(w.x); al[mt][1] = __float_as_uint(w.y);
            al[mt][2] = __float_as_uint(w.z); al[mt][3] = __float_as_uint(w.w);
        }
#pragma unroll
        for (int nt = 0; nt < 4; nt++) {
            const float2 v = *(const float2*)(Bh + (((ks * 16 + (wn * 4 + nt)) * 32 + lsw) << 1));
            bf[nt][0] = __float_as_uint(v.x); bf[nt][1] = __float_as_uint(v.y);
            const float2 w = *(const float2*)(Bl + (((ks * 16 + (wn * 4 + nt)) * 32 + lsw) << 1));
            bl[nt][0] = __float_as_uint(w.x); bl[nt][1] = __float_as_uint(w.y);
        }
#pragma unroll
        for (int mt = 0; mt < 4; mt++)
#pragma unroll
            for (int nt = 0; nt < 4; nt++) {
                mma_tf32(acc[mt][nt], af[mt], bf[nt]);
                mma_tf32(acc[mt][nt], al[mt], bf[nt]);
                mma_tf32(acc[mt][nt], af[mt], bl[nt]);
            }
    }
}

__global__ void __launch_bounds__(256)
gemm_comp(const float* __restrict__ A, const float* __restrict__ B,
          float* __restrict__ C, int M, int N, int K,
          const float* __restrict__ bias, int flags) {
    extern __shared__ float smemf[];
    float* const s0 = smemf;
    float* const s1 = smemf + STG_COMP;

    const int tid  = threadIdx.x;
    const int lane = tid & 31;
    const int warp = tid >> 5;
    const int wm = warp >> 2;
    const int wn = warp & 3;
    const int m0 = blockIdx.x * 128;
    const int n0 = blockIdx.y * 128;

    float acc[4][4][4];
#pragma unroll
    for (int i = 0; i < 4; i++)
#pragma unroll
        for (int j = 0; j < 4; j++)
#pragma unroll
            for (int s = 0; s < 4; s++) acc[i][j][s] = 0.0f;

    const int lrow = tid >> 3;
    const int lk4  = (tid & 7) * 4;
    const int nK = K >> 5;

    float4 pa[4], pb[4];

    load_tile128(A, B, M, N, K, m0, n0, lk4, lrow, pa, pb);
    store_stage128(s0, pa, pb, lrow, lk4);
    __syncthreads();

    for (int kt = 0; kt < nK; kt += 2) {
        if (kt + 1 < nK)
            load_tile128(A, B, M, N, K, m0, n0, (kt + 1) * 32 + lk4, lrow, pa, pb);
        compute_stage128(s0, acc, wm, wn, lane);
        if (kt + 1 < nK) {
            store_stage128(s1, pa, pb, lrow, lk4);
            __syncthreads();

            if (kt + 2 < nK)
                load_tile128(A, B, M, N, K, m0, n0, (kt + 2) * 32 + lk4, lrow, pa, pb);
            compute_stage128(s1, acc, wm, wn, lane);
            if (kt + 2 < nK) {
                store_stage128(s0, pa, pb, lrow, lk4);
                __syncthreads();
            }
        }
    }

    const int row = lane >> 2;
    const int col = (lane & 3) * 2;
#pragma unroll
    for (int mt = 0; mt < 4; mt++) {
#pragma unroll
        for (int nt = 0; nt < 4; nt++) {
#pragma unroll
            for (int s = 0; s < 4; s++) {
                int gm = m0 + wm * 64 + mt * 16 + row + ((s >> 1) ? 8 : 0);
                int gn = n0 + wn * 32 + nt * 8 + col + (s & 1);
                if (gm >= M || gn >= N) continue;
                float v = acc[mt][nt][s];
                if (flags & 1) v += bias[gn];
                if (flags & 2) v = tanhf(v);
                C[(size_t)gm * (size_t)N + (size_t)gn] = v;
            }
        }
    }
}

// ---------------- fused h0 kernel (zero initial state) ----------------
__global__ __launch_bounds__(256)
void gru_h0(const float* __restrict__ Wih, const float* __restrict__ bih,
            const float* __restrict__ bhh,
            const float* __restrict__ x,      // BB x HH
            float* __restrict__ hout) {       // BB x HH
    const int warp = threadIdx.x >> 5;
    const int lane = threadIdx.x & 31;
    const int j = blockIdx.x * 8 + warp;

    float accr[BB], accz[BB], accn[BB];
#pragma unroll
    for (int b = 0; b < BB; b++) { accr[b] = 0.f; accz[b] = 0.f; accn[b] = 0.f; }

    const float4* wr = (const float4*)(Wih + (size_t)j * HH);
    const float4* wz = (const float4*)(Wih + (size_t)(HH + j) * HH);
    const float4* wn = (const float4*)(Wih + (size_t)(2 * HH + j) * HH);
    const float4* x4 = (const float4*)x;

#pragma unroll
    for (int it = 0; it < 8; it++) {
        int k4 = it * 32 + lane;
        float4 a = wr[k4];
        float4 bq = wz[k4];
        float4 c = wn[k4];
#pragma unroll
        for (int b = 0; b < BB; b++) {
            float4 hv = x4[b * 256 + k4];
            accr[b] = fmaf(a.x, hv.x, fmaf(a.y, hv.y, fmaf(a.z, hv.z, fmaf(a.w, hv.w, accr[b]))));
            accz[b] = fmaf(bq.x, hv.x, fmaf(bq.y, hv.y, fmaf(bq.z, hv.z, fmaf(bq.w, hv.w, accz[b]))));
            accn[b] = fmaf(c.x, hv.x, fmaf(c.y, hv.y, fmaf(c.z, hv.z, fmaf(c.w, hv.w, accn[b]))));
        }
    }

    float sr = 0.f, sz = 0.f, sn = 0.f;
#pragma unroll
    for (int b = 0; b < BB; b++) {
        float r = accr[b], z = accz[b], n = accn[b];
#pragma unroll
        for (int off = 16; off > 0; off >>= 1) {
            r += __shfl_xor_sync(0xFFFFFFFFu, r, off);
            z += __shfl_xor_sync(0xFFFFFFFFu, z, off);
            n += __shfl_xor_sync(0xFFFFFFFFu, n, off);
        }
        if (lane == b) { sr = r; sz = z; sn = n; }
    }

    if (lane < BB) {
        float xr = sr + bih[j];
        float xz = sz + bih[HH + j];
        float xn = sn + bih[2 * HH + j];
        float r = 1.f / (1.f + expf(-(xr + bhh[j])));
        float z = 1.f / (1.f + expf(-(xz + bhh[HH + j])));
        float n = tanhf(xn + r * bhh[2 * HH + j]);
        hout[lane * HH + j] = (1.f - z) * n;
    }
}

// ---------------- persistent GRU scan (one layer, all 64 steps) ----------------
__device__ __forceinline__ void grid_barrier() {
    __syncthreads();
    if (threadIdx.x == 0) {
        __threadfence();
        unsigned gen = atomicAdd(&g_bar_gen, 0u);
        unsigned arrived = atomicAdd(&g_bar_count, 1u);
        if (arrived == NCTA_SCAN - 1) {
            g_bar_count = 0;
            __threadfence();
            atomicAdd(&g_bar_gen, 1u);
        } else {
            while (atomicAdd(&g_bar_gen, 0u) == gen) { __nanosleep(32); }
        }
    }
    __syncthreads();
}

__global__ void __launch_bounds__(256)
gru_scan(const float* __restrict__ Whh, const float* __restrict__ bhh,
         const float* __restrict__ xp,    // TT x BB x 3H (includes b_ih)
         const float* __restrict__ h0,    // BB x HH
         float* __restrict__ ys) {        // TT x BB x HH
    extern __shared__ float hs[];         // BB*HH floats = 64 KB
    const int tid  = threadIdx.x;
    const int warp = tid >> 5;
    const int lane = tid & 31;
    const int j = blockIdx.x * 8 + warp;

    const ulonglong2* wr2 = (const ulonglong2*)(Whh + (size_t)j * HH);
    const ulonglong2* wz2 = (const ulonglong2*)(Whh + (size_t)(HH + j) * HH);
    const ulonglong2* wn2 = (const ulonglong2*)(Whh + (size_t)(2 * HH + j) * HH);
    ulonglong2 wcr[8], wcz[8], wcn[8];
#pragma unroll
    for (int it = 0; it < 8; it++) {
        int idx = it * 32 + lane;
        wcr[it] = wr2[idx];
        wcz[it] = wz2[idx];
        wcn[it] = wn2[idx];
    }
    const float bhr = bhh[j];
    const float bhz = bhh[HH + j];
    const float bhn = bhh[2 * HH + j];

    for (int t = 0; t < TT; t++) {
        const float4* hp4 = (const float4*)((t == 0) ? h0 : (ys + (size_t)(t - 1) * BB * HH));
#pragma unroll 4
        for (int idx = tid; idx < BB * HH / 4; idx += 256)
            ((float4*)hs)[idx] = hp4[idx];
        __syncthreads();

        unsigned long long ar[BB], az[BB], an[BB];
#pragma unroll
        for (int b = 0; b < BB; b++) { ar[b] = 0ull; az[b] = 0ull; an[b] = 0ull; }

        const ulonglong2* h2 = (const ulonglong2*)hs;
#pragma unroll
        for (int it = 0; it < 8; it++) {
            int idx = it * 32 + lane;
            ulonglong2 a = wcr[it], bq = wcz[it], c = wcn[it];
#pragma unroll
            for (int b = 0; b < BB; b++) {
                ulonglong2 hv = h2[b * 256 + idx];
                fma2(ar[b], a.x,  hv.x); fma2(ar[b], a.y,  hv.y);
                fma2(az[b], bq.x, hv.x); fma2(az[b], bq.y, hv.y);
                fma2(an[b], c.x,  hv.x); fma2(an[b], c.y,  hv.y);
            }
        }

        float sr = 0.f, sz = 0.f, sn = 0.f;
#pragma unroll
        for (int b = 0; b < BB; b++) {
            float r = f32x2_sum(ar[b]);
            float z = f32x2_sum(az[b]);
            float n = f32x2_sum(an[b]);
#pragma unroll
            for (int off = 16; off > 0; off >>= 1) {
                r += __shfl_xor_sync(0xFFFFFFFFu, r, off);
                z += __shfl_xor_sync(0xFFFFFFFFu, z, off);
                n += __shfl_xor_sync(0xFFFFFFFFu, n, off);
            }
            if (lane == b) { sr = r; sz = z; sn = n; }
        }

        if (lane < BB) {
            int b = lane;
            const float* xg = xp + (size_t)t * BB * G3H + (size_t)b * G3H;
            float xr = xg[j];
            float xz = xg[HH + j];
            float xn = xg[2 * HH + j];
            float hp = hs[b * HH + j];
            float r = 1.f / (1.f + expf(-(xr + sr + bhr)));
            float z = 1.f / (1.f + expf(-(xz + sz + bhz)));
            float n = tanhf(xn + r * (sn + bhn));
            ys[(size_t)t * BB * HH + b * HH + j] = (1.f - z) * n + z * hp;
        }

        if (t < TT - 1)
            grid_barrier();
    }
}

// ---------------- host orchestration ----------------
#define SMEM_G64   (2 * STG64 * 4)      // 48 KB
#define SMEM_COMP  (2 * STG_COMP * 4)   // 128 KB
#define SMEM_SCAN  (BB * HH * 4)        // 64 KB

extern "C" void kernel_launch(void* const* d_in, const int* in_sizes, int n_in,
                              void* d_out, int out_size) {
    const float* init  = (const float*)d_in[0];
    const int*   helper= (const int*)  d_in[1];
    const float* emb   = (const float*)d_in[2];
    const float* W_ih0 = (const float*)d_in[3];
    const float* W_hh0 = (const float*)d_in[4];
    const float* b_ih0 = (const float*)d_in[5];
    const float* b_hh0 = (const float*)d_in[6];
    const float* W_ih1 = (const float*)d_in[7];
    const float* W_hh1 = (const float*)d_in[8];
    const float* b_ih1 = (const float*)d_in[9];
    const float* b_hh1 = (const float*)d_in[10];
    const float* Wc_w  = (const float*)d_in[11];
    const float* Wc_b  = (const float*)d_in[12];
    float* out = (float*)d_out;

    float *x0, *h0a, *h0b, *xdec, *xp, *ys0, *ys1, *fin;
    cudaGetSymbolAddress((void**)&x0,   g_x0);
    cudaGetSymbolAddress((void**)&h0a,  g_h0a);
    cudaGetSymbolAddress((void**)&h0b,  g_h0b);
    cudaGetSymbolAddress((void**)&xdec, g_xdec);
    cudaGetSymbolAddress((void**)&xp,   g_xp);
    cudaGetSymbolAddress((void**)&ys0,  g_ys0);
    cudaGetSymbolAddress((void**)&ys1,  g_ys1);
    cudaGetSymbolAddress((void**)&fin,  g_final);

    cudaFuncSetAttribute(gemm64,    cudaFuncAttributeMaxDynamicSharedMemorySize, SMEM_G64);
    cudaFuncSetAttribute(gemm_comp, cudaFuncAttributeMaxDynamicSharedMemorySize, SMEM_COMP);
    cudaFuncSetAttribute(gru_scan,  cudaFuncAttributeMaxDynamicSharedMemorySize, SMEM_SCAN);

    dim3 blk(256);

    // ---- h0 (fused small path) ----
    build_x0<<<BB, blk>>>(init, x0);
    gru_h0<<<128, blk>>>(W_ih0, b_ih0, b_hh0, x0, h0a);
    gru_h0<<<128, blk>>>(W_ih1, b_ih1, b_hh1, h0a, h0b);

    // ---- decoder inputs ----
    build_xdec<<<TT * BB, blk>>>(helper, emb, init, xdec);

    // ---- layer 0: xp (64-tile, single-pass tf32) then persistent scan ----
    gemm64<<<dim3(TT * BB / 64, G3H / 128), blk, SMEM_G64>>>(
        xdec, W_ih0, xp, TT * BB, G3H, 2 * EE, b_ih0, 1);
    gru_scan<<<NCTA_SCAN, blk, SMEM_SCAN>>>(W_hh0, b_hh0, xp, h0a, ys0);

    // ---- layer 1: xp then persistent scan ----
    gemm64<<<dim3(TT * BB / 64, G3H / 128), blk, SMEM_G64>>>(
        ys0, W_ih1, xp, TT * BB, G3H, HH, b_ih1, 1);
    gru_scan<<<NCTA_SCAN, blk, SMEM_SCAN>>>(W_hh1, b_hh1, xp, h0b, ys1);

    // ---- final = tanh(ys1 @ Wc_w^T + Wc_b), compensated 128-tile ----
    gemm_comp<<<dim3(TT * BB / 128, EE / 128), blk, SMEM_COMP>>>(
        ys1, Wc_w, fin, TT * BB, EE, HH, Wc_b, 1 | 2);

    // ---- logits = final @ emb^T (64-tile, single-pass tf32, (b,t) store) ----
    gemm64<<<dim3(TT * BB / 64, (VV + 127) / 128), blk, SMEM_G64>>>(
        fin, emb, out, TT * BB, VV, EE, nullptr, 4);
}

// round 16
// speedup vs baseline: 1.5003x; 1.0369x over previous
#include <cuda_runtime.h>
#include <cuda_bf16.h>
#include <math.h>
#include <stdint.h>

// Problem constants
#define BB 16      // batch
#define TT 64      // seq len
#define VV 50257   // vocab
#define EE 512     // embed
#define HH 1024    // hidden
#define G3H 3072   // 3*H

#define NCTA_SCAN 128   // persistent scan grid (<=148 SMs -> all resident)

// ---------------- scratch (no allocations allowed) ----------------
__device__ float g_h0a[BB * HH];             // layer0 h0
__device__ float g_h0b[BB * HH];             // layer1 h0
__device__ float g_xdec[TT * BB * 2 * EE];   // 1024x1024
__device__ float g_xp[TT * BB * G3H];        // 1024x3072 (reused for both layers)
__device__ float g_ys0[TT * BB * HH];        // 1024x1024
__device__ float g_ys1[TT * BB * HH];        // 1024x1024
__device__ float g_final[TT * BB * EE];      // 1024x512

// grid-barrier state (self-restoring: count returns to 0; gen compared by equality)
__device__ unsigned g_bar_count = 0;
__device__ unsigned g_bar_gen   = 0;

// ---------------- builder ----------------
__global__ void build_xdec(const int* __restrict__ helper,
                           const float* __restrict__ emb,
                           const float* __restrict__ init,
                           float* __restrict__ xdec) {
    int r = blockIdx.x;            // r = t*B + b
    int t = r >> 4;
    int b = r & 15;
    int tok = helper[b * TT + t];
    const float* src0 = emb + (size_t)tok * EE;
    const float* src1 = init + b * EE;
    float* dst = xdec + (size_t)r * (2 * EE);
    for (int c = threadIdx.x; c < EE; c += blockDim.x) {
        dst[c] = src0[c];
        dst[EE + c] = src1[c];
    }
}

// ---------------- tf32 / f32x2 helpers ----------------
__device__ __forceinline__ uint32_t f2tf32(float x) {
    uint32_t r;
    asm("cvt.rna.tf32.f32 %0, %1;" : "=r"(r) : "f"(x));
    return r;
}

__device__ __forceinline__ void mma_tf32(float* c, const uint32_t* a, const uint32_t* b) {
    asm volatile(
        "mma.sync.aligned.m16n8k8.row.col.f32.tf32.tf32.f32 "
        "{%0,%1,%2,%3}, {%4,%5,%6,%7}, {%8,%9}, {%0,%1,%2,%3};"
        : "+f"(c[0]), "+f"(c[1]), "+f"(c[2]), "+f"(c[3])
        : "r"(a[0]), "r"(a[1]), "r"(a[2]), "r"(a[3]), "r"(b[0]), "r"(b[1]));
}

// packed fp32x2 FMA (sm_100+; PTX-only, ptxas never auto-fuses)
__device__ __forceinline__ void fma2(unsigned long long& d,
                                     unsigned long long a, unsigned long long b) {
    asm("fma.rn.f32x2 %0, %1, %2, %3;" : "=l"(d) : "l"(a), "l"(b), "l"(d));
}
__device__ __forceinline__ float f32x2_sum(unsigned long long v) {
    float lo, hi;
    asm("mov.b64 {%0,%1}, %2;" : "=f"(lo), "=f"(hi) : "l"(v));
    return lo + hi;
}

// =======================================================================
// 64x128 GEMM (xp + final + logits): C = A(MxK) * B(NxK)^T
// Block tile 64(M) x 128(N), K tile 32. 8 warps as 2(m) x 4(n), warp 32x32.
// No launch_bounds min-blocks: ~110 regs -> 2 CTAs/SM naturally.
// Double-buffered compile-time stages, ks-XOR swizzle, grid x=M (fast).
// flags: bit0 = add bias[n]; bit1 = tanh; bit2 = (b,t) transposed store
// =======================================================================
#define STG64 6144   // floats per stage: A(2048)+B(4096)

__device__ __forceinline__ void load_tile64(
    const float* __restrict__ A, const float* __restrict__ B,
    int M, int N, int K, int m0, int n0, int kbase, int lrow,
    float4* pa, float4* pb) {
#pragma unroll
    for (int p = 0; p < 2; p++) {
        int gr = m0 + lrow + p * 32;
        pa[p] = (gr < M) ? *(const float4*)&A[(size_t)gr * K + kbase]
                         : make_float4(0.f, 0.f, 0.f, 0.f);
    }
#pragma unroll
    for (int p = 0; p < 4; p++) {
        int gn = n0 + lrow + p * 32;
        pb[p] = (gn < N) ? *(const float4*)&B[(size_t)gn * K + kbase]
                         : make_float4(0.f, 0.f, 0.f, 0.f);
    }
}

__device__ __forceinline__ void store_stage64(
    float* stage, const float4* pa, const float4* pb, int lrow, int lk4) {
    float* Ah = stage;            // [ks4][mt4][ln32][slot4] = 2048
    float* Bh = stage + 2048;     // [ks4][nt16][ln32][slot2] = 4096
#pragma unroll
    for (int p = 0; p < 2; p++) {
        int m = lrow + p * 32;
        const float* av = (const float*)&pa[p];
#pragma unroll
        for (int i = 0; i < 4; i++) {
            int k = lk4 + i;
            int ks = k >> 3, kc = k & 7;
            int mt = m >> 4, r = m & 15;
            int ln = (((r & 7) << 2) | (kc & 3)) ^ ks;
            int slot = (r >> 3) | ((kc >> 2) << 1);
            int idx = (((ks * 4 + mt) * 32 + ln) << 2) | slot;
            Ah[idx] = __uint_as_float(f2tf32(av[i]));
        }
    }
#pragma unroll
    for (int p = 0; p < 4; p++) {
        int n = lrow + p * 32;
        const float* bv = (const float*)&pb[p];
#pragma unroll
        for (int i = 0; i < 4; i++) {
            int k = lk4 + i;
            int ks = k >> 3, kc = k & 7;
            int nt = n >> 3;
            int ln = (((n & 7) << 2) | (kc & 3)) ^ ks;
            int slot = kc >> 2;
            int idx = (((ks * 16 + nt) * 32 + ln) << 1) | slot;
            Bh[idx] = __uint_as_float(f2tf32(bv[i]));
        }
    }
}

__device__ __forceinline__ void compute_stage64(
    const float* stage, float acc[2][4][4], int wm, int wn, int lane) {
    const float* Ah = stage;
    const float* Bh = stage + 2048;
#pragma unroll
    for (int ks = 0; ks < 4; ks++) {
        const int lsw = lane ^ ks;
        uint32_t af[2][4], bf[4][2];
#pragma unroll
        for (int mt = 0; mt < 2; mt++) {
            const float4 v = *(const float4*)(Ah + (((ks * 4 + (wm * 2 + mt)) * 32 + lsw) << 2));
            af[mt][0] = __float_as_uint(v.x); af[mt][1] = __float_as_uint(v.y);
            af[mt][2] = __float_as_uint(v.z); af[mt][3] = __float_as_uint(v.w);
        }
#pragma unroll
        for (int nt = 0; nt < 4; nt++) {
            const float2 v = *(const float2*)(Bh + (((ks * 16 + (wn * 4 + nt)) * 32 + lsw) << 1));
            bf[nt][0] = __float_as_uint(v.x); bf[nt][1] = __float_as_uint(v.y);
        }
#pragma unroll
        for (int mt = 0; mt < 2; mt++)
#pragma unroll
            for (int nt = 0; nt < 4; nt++)
                mma_tf32(acc[mt][nt], af[mt], bf[nt]);
    }
}

__global__ void __launch_bounds__(256)
gemm64(const float* __restrict__ A, const float* __restrict__ B,
       float* __restrict__ C, int M, int N, int K,
       const float* __restrict__ bias, int flags) {
    extern __shared__ float smemf[];
    float* const s0 = smemf;
    float* const s1 = smemf + STG64;

    const int tid  = threadIdx.x;
    const int lane = tid & 31;
    const int warp = tid >> 5;
    const int wm = warp >> 2;     // 0..1
    const int wn = warp & 3;      // 0..3
    const int m0 = blockIdx.x * 64;
    const int n0 = blockIdx.y * 128;

    float acc[2][4][4];
#pragma unroll
    for (int i = 0; i < 2; i++)
#pragma unroll
        for (int j = 0; j < 4; j++)
#pragma unroll
            for (int s = 0; s < 4; s++) acc[i][j][s] = 0.0f;

    const int lrow = tid >> 3;        // 0..31
    const int lk4  = (tid & 7) * 4;   // 0,4,...,28
    const int nK = K >> 5;            // even at all call sites

    float4 pa[2], pb[4];

    load_tile64(A, B, M, N, K, m0, n0, lk4, lrow, pa, pb);
    store_stage64(s0, pa, pb, lrow, lk4);
    __syncthreads();

    for (int kt = 0; kt < nK; kt += 2) {
        if (kt + 1 < nK)
            load_tile64(A, B, M, N, K, m0, n0, (kt + 1) * 32 + lk4, lrow, pa, pb);
        compute_stage64(s0, acc, wm, wn, lane);
        if (kt + 1 < nK) {
            store_stage64(s1, pa, pb, lrow, lk4);
            __syncthreads();

            if (kt + 2 < nK)
                load_tile64(A, B, M, N, K, m0, n0, (kt + 2) * 32 + lk4, lrow, pa, pb);
            compute_stage64(s1, acc, wm, wn, lane);
            if (kt + 2 < nK) {
                store_stage64(s0, pa, pb, lrow, lk4);
                __syncthreads();
            }
        }
    }

    const int row = lane >> 2;
    const int col = (lane & 3) * 2;
#pragma unroll
    for (int mt = 0; mt < 2; mt++) {
#pragma unroll
        for (int nt = 0; nt < 4; nt++) {
#pragma unroll
            for (int s = 0; s < 4; s++) {
                int gm = m0 + (wm * 2 + mt) * 16 + row + ((s >> 1) ? 8 : 0);
                int gn = n0 + (wn * 4 + nt) * 8 + col + (s & 1);
                if (gm >= M || gn >= N) continue;
                float v = acc[mt][nt][s];
                if (flags & 1) v += bias[gn];
                if (flags & 2) v = tanhf(v);
                size_t idx;
                if (flags & 4) {
                    int b = gm & 15;     // gm = t*16 + b
                    int t = gm >> 4;
                    idx = (size_t)(b * TT + t) * (size_t)N + (size_t)gn;
                } else {
                    idx = (size_t)gm * (size_t)N + (size_t)gn;
                }
                C[idx] = v;
            }
        }
    }
}

// ---------------- fused h0 kernel (zero initial state) ----------------
// dup=1: x is conceptually cat(init, init) (BB x 2E) but we read init
//        (BB x EE) directly with k mod EE indexing (removes build_x0).
// dup=0: x is a full BB x HH matrix (layer 1: h0a).
__global__ __launch_bounds__(256)
void gru_h0(const float* __restrict__ Wih, const float* __restrict__ bih,
            const float* __restrict__ bhh,
            const float* __restrict__ x,      // BB x EE (dup) or BB x HH
            float* __restrict__ hout,         // BB x HH
            int dup) {
    const int warp = threadIdx.x >> 5;
    const int lane = threadIdx.x & 31;
    const int j = blockIdx.x * 8 + warp;

    float accr[BB], accz[BB], accn[BB];
#pragma unroll
    for (int b = 0; b < BB; b++) { accr[b] = 0.f; accz[b] = 0.f; accn[b] = 0.f; }

    const float4* wr = (const float4*)(Wih + (size_t)j * HH);
    const float4* wz = (const float4*)(Wih + (size_t)(HH + j) * HH);
    const float4* wn = (const float4*)(Wih + (size_t)(2 * HH + j) * HH);
    const float4* x4 = (const float4*)x;
    const int xstride = dup ? 128 : 256;   // float4s per batch row
    const int xmask   = dup ? 127 : 255;

#pragma unroll
    for (int it = 0; it < 8; it++) {
        int k4 = it * 32 + lane;
        int xk = k4 & xmask;
        float4 a = wr[k4];
        float4 bq = wz[k4];
        float4 c = wn[k4];
#pragma unroll
        for (int b = 0; b < BB; b++) {
            float4 hv = x4[b * xstride + xk];
            accr[b] = fmaf(a.x, hv.x, fmaf(a.y, hv.y, fmaf(a.z, hv.z, fmaf(a.w, hv.w, accr[b]))));
            accz[b] = fmaf(bq.x, hv.x, fmaf(bq.y, hv.y, fmaf(bq.z, hv.z, fmaf(bq.w, hv.w, accz[b]))));
            accn[b] = fmaf(c.x, hv.x, fmaf(c.y, hv.y, fmaf(c.z, hv.z, fmaf(c.w, hv.w, accn[b]))));
        }
    }

    float sr = 0.f, sz = 0.f, sn = 0.f;
#pragma unroll
    for (int b = 0; b < BB; b++) {
        float r = accr[b], z = accz[b], n = accn[b];
#pragma unroll
        for (int off = 16; off > 0; off >>= 1) {
            r += __shfl_xor_sync(0xFFFFFFFFu, r, off);
            z += __shfl_xor_sync(0xFFFFFFFFu, z, off);
            n += __shfl_xor_sync(0xFFFFFFFFu, n, off);
        }
        if (lane == b) { sr = r; sz = z; sn = n; }
    }

    if (lane < BB) {
        float xr = sr + bih[j];
        float xz = sz + bih[HH + j];
        float xn = sn + bih[2 * HH + j];
        float r = 1.f / (1.f + expf(-(xr + bhh[j])));
        float z = 1.f / (1.f + expf(-(xz + bhh[HH + j])));
        float n = tanhf(xn + r * bhh[2 * HH + j]);
        hout[lane * HH + j] = (1.f - z) * n;
    }
}

// ---------------- persistent GRU scan (one layer, all 64 steps) ----------------
__device__ __forceinline__ void grid_barrier() {
    __syncthreads();
    if (threadIdx.x == 0) {
        __threadfence();
        unsigned gen = atomicAdd(&g_bar_gen, 0u);
        unsigned arrived = atomicAdd(&g_bar_count, 1u);
        if (arrived == NCTA_SCAN - 1) {
            g_bar_count = 0;
            __threadfence();
            atomicAdd(&g_bar_gen, 1u);
        } else {
            while (atomicAdd(&g_bar_gen, 0u) == gen) { __nanosleep(32); }
        }
    }
    __syncthreads();
}

__global__ void __launch_bounds__(256)
gru_scan(const float* __restrict__ Whh, const float* __restrict__ bhh,
         const float* __restrict__ xp,    // TT x BB x 3H (includes b_ih)
         const float* __restrict__ h0,    // BB x HH
         float* __restrict__ ys) {        // TT x BB x HH
    extern __shared__ float hs[];         // BB*HH floats = 64 KB
    const int tid  = threadIdx.x;
    const int warp = tid >> 5;
    const int lane = tid & 31;
    const int j = blockIdx.x * 8 + warp;

    const ulonglong2* wr2 = (const ulonglong2*)(Whh + (size_t)j * HH);
    const ulonglong2* wz2 = (const ulonglong2*)(Whh + (size_t)(HH + j) * HH);
    const ulonglong2* wn2 = (const ulonglong2*)(Whh + (size_t)(2 * HH + j) * HH);
    ulonglong2 wcr[8], wcz[8], wcn[8];
#pragma unroll
    for (int it = 0; it < 8; it++) {
        int idx = it * 32 + lane;
        wcr[it] = wr2[idx];
        wcz[it] = wz2[idx];
        wcn[it] = wn2[idx];
    }
    const float bhr = bhh[j];
    const float bhz = bhh[HH + j];
    const float bhn = bhh[2 * HH + j];

    for (int t = 0; t < TT; t++) {
        const float4* hp4 = (const float4*)((t == 0) ? h0 : (ys + (size_t)(t - 1) * BB * HH));
#pragma unroll 4
        for (int idx = tid; idx < BB * HH / 4; idx += 256)
            ((float4*)hs)[idx] = hp4[idx];
        __syncthreads();

        unsigned long long ar[BB], az[BB], an[BB];
#pragma unroll
        for (int b = 0; b < BB; b++) { ar[b] = 0ull; az[b] = 0ull; an[b] = 0ull; }

        const ulonglong2* h2 = (const ulonglong2*)hs;
#pragma unroll
        for (int it = 0; it < 8; it++) {
            int idx = it * 32 + lane;
            ulonglong2 a = wcr[it], bq = wcz[it], c = wcn[it];
#pragma unroll
            for (int b = 0; b < BB; b++) {
                ulonglong2 hv = h2[b * 256 + idx];
                fma2(ar[b], a.x,  hv.x); fma2(ar[b], a.y,  hv.y);
                fma2(az[b], bq.x, hv.x); fma2(az[b], bq.y, hv.y);
                fma2(an[b], c.x,  hv.x); fma2(an[b], c.y,  hv.y);
            }
        }

        float sr = 0.f, sz = 0.f, sn = 0.f;
#pragma unroll
        for (int b = 0; b < BB; b++) {
            float r = f32x2_sum(ar[b]);
            float z = f32x2_sum(az[b]);
            float n = f32x2_sum(an[b]);
#pragma unroll
            for (int off = 16; off > 0; off >>= 1) {
                r += __shfl_xor_sync(0xFFFFFFFFu, r, off);
                z += __shfl_xor_sync(0xFFFFFFFFu, z, off);
                n += __shfl_xor_sync(0xFFFFFFFFu, n, off);
            }
            if (lane == b) { sr = r; sz = z; sn = n; }
        }

        if (lane < BB) {
            int b = lane;
            const float* xg = xp + (size_t)t * BB * G3H + (size_t)b * G3H;
            float xr = xg[j];
            float xz = xg[HH + j];
            float xn = xg[2 * HH + j];
            float hp = hs[b * HH + j];
            float r = 1.f / (1.f + expf(-(xr + sr + bhr)));
            float z = 1.f / (1.f + expf(-(xz + sz + bhz)));
            float n = tanhf(xn + r * (sn + bhn));
            ys[(size_t)t * BB * HH + b * HH + j] = (1.f - z) * n + z * hp;
        }

        if (t < TT - 1)
            grid_barrier();
    }
}

// ---------------- host orchestration ----------------
#define SMEM_G64   (2 * STG64 * 4)      // 48 KB
#define SMEM_SCAN  (BB * HH * 4)        // 64 KB

extern "C" void kernel_launch(void* const* d_in, const int* in_sizes, int n_in,
                              void* d_out, int out_size) {
    const float* init  = (const float*)d_in[0];
    const int*   helper= (const int*)  d_in[1];
    const float* emb   = (const float*)d_in[2];
    const float* W_ih0 = (const float*)d_in[3];
    const float* W_hh0 = (const float*)d_in[4];
    const float* b_ih0 = (const float*)d_in[5];
    const float* b_hh0 = (const float*)d_in[6];
    const float* W_ih1 = (const float*)d_in[7];
    const float* W_hh1 = (const float*)d_in[8];
    const float* b_ih1 = (const float*)d_in[9];
    const float* b_hh1 = (const float*)d_in[10];
    const float* Wc_w  = (const float*)d_in[11];
    const float* Wc_b  = (const float*)d_in[12];
    float* out = (float*)d_out;

    float *h0a, *h0b, *xdec, *xp, *ys0, *ys1, *fin;
    cudaGetSymbolAddress((void**)&h0a,  g_h0a);
    cudaGetSymbolAddress((void**)&h0b,  g_h0b);
    cudaGetSymbolAddress((void**)&xdec, g_xdec);
    cudaGetSymbolAddress((void**)&xp,   g_xp);
    cudaGetSymbolAddress((void**)&ys0,  g_ys0);
    cudaGetSymbolAddress((void**)&ys1,  g_ys1);
    cudaGetSymbolAddress((void**)&fin,  g_final);

    cudaFuncSetAttribute(gemm64,   cudaFuncAttributeMaxDynamicSharedMemorySize, SMEM_G64);
    cudaFuncSetAttribute(gru_scan, cudaFuncAttributeMaxDynamicSharedMemorySize, SMEM_SCAN);

    dim3 blk(256);

    // ---- h0 (fused small path; layer0 reads init directly with dup) ----
    gru_h0<<<128, blk>>>(W_ih0, b_ih0, b_hh0, init, h0a, 1);
    gru_h0<<<128, blk>>>(W_ih1, b_ih1, b_hh1, h0a, h0b, 0);

    // ---- decoder inputs ----
    build_xdec<<<TT * BB, blk>>>(helper, emb, init, xdec);

    // ---- layer 0: xp (64-tile, single-pass tf32) then persistent scan ----
    gemm64<<<dim3(TT * BB / 64, G3H / 128), blk, SMEM_G64>>>(
        xdec, W_ih0, xp, TT * BB, G3H, 2 * EE, b_ih0, 1);
    gru_scan<<<NCTA_SCAN, blk, SMEM_SCAN>>>(W_hh0, b_hh0, xp, h0a, ys0);

    // ---- layer 1: xp then persistent scan ----
    gemm64<<<dim3(TT * BB / 64, G3H / 128), blk, SMEM_G64>>>(
        ys0, W_ih1, xp, TT * BB, G3H, HH, b_ih1, 1);
    gru_scan<<<NCTA_SCAN, blk, SMEM_SCAN>>>(W_hh1, b_hh1, xp, h0b, ys1);

    // ---- final = tanh(ys1 @ Wc_w^T + Wc_b), single-pass tf32 64-tile ----
    gemm64<<<dim3(TT * BB / 64, EE / 128), blk, SMEM_G64>>>(
        ys1, Wc_w, fin, TT * BB, EE, HH, Wc_b, 1 | 2);

    // ---- logits = final @ emb^T (64-tile, single-pass tf32, (b,t) store) ----
    gemm64<<<dim3(TT * BB / 64, (VV + 127) / 128), blk, SMEM_G64>>>(
        fin, emb, out, TT * BB, VV, EE, nullptr, 4);
}